// round 12
// baseline (speedup 1.0000x reference)
#include <cuda_runtime.h>

#define EPT 4   // edge pairs prefetched per thread (Eg/nt == 4 here; guarded anyway)

// ---------------------------------------------------------------------------
// Single fused kernel: one CTA (1024 thr) per graph.
// Phase 1: dual dot products with the PROVEN 8-lane/4-node coalesced layout
//          (weights in smem) -> p_s, r_s in smem. Edge list prefetched to regs.
// Phase 2: edge scatter-add via smem atomics (pure LDS+ATOMS).
// Phase 3: tanh -> monotone bits -> histogram top-k (exact, jax tie-break).
// Phase 4: float4 weighted-mean gather (rows L1/L2-hot from phase 1).
// Phase 5: vectorized projection.
// ---------------------------------------------------------------------------
__global__ __launch_bounds__(1024, 1)
void k_fused(const float* __restrict__ x,
             const int* __restrict__ ei,
             const float4* __restrict__ wrel4,
             const float* __restrict__ brel,
             const float4* __restrict__ wroot4,
             const float* __restrict__ wproj,
             const float* __restrict__ bproj,
             float* __restrict__ out,
             int n, int k, int d, int odim, int E, int Eg, int nrep4) {
    extern __shared__ unsigned char sm[];
    float4* wsm    = (float4*)sm;                                // 2 * d4
    float* p_s     = (float*)(wsm + 2 * (d >> 2));               // n
    float* r_s     = p_s + n;                                    // n
    float* agg_s   = r_s + n;                                    // n
    float* svals   = agg_s + n;                                  // k
    int*   sidx    = (int*)(svals + k);                          // k
    unsigned* hist = (unsigned*)(sidx + k);                      // 256
    unsigned* wtot = hist + 256;                                 // 8
    uint2* list    = (uint2*)(wtot + 8);                         // n
    float* part    = (float*)(list + n);                         // nrep4 * d
    float* pooled  = part + nrep4 * d;                           // d
    int*   ctrl    = (int*)(pooled + d);                         // cnt, m, tb, krem

    const int g    = blockIdx.x;
    const int t    = threadIdx.x;
    const int base = g * n;
    const int nt   = blockDim.x;
    const int d4   = d >> 2;

    // ---- prefetch edge list into registers (independent of phase 1) ----
    int es[EPT], ed[EPT];
    {
        const int eb = g * Eg;
#pragma unroll
        for (int q = 0; q < EPT; q++) {
            int e = t + q * nt;
            if (e < Eg) {
                es[q] = ei[eb + e] - base;
                ed[q] = ei[E + eb + e] - base;
            } else { es[q] = 0; ed[q] = -1; }
        }
    }
    const float br = brel[0];

    // ---- init smem ----
    if (t < 4) ctrl[t] = 0;
    for (int b = t; b < 256; b += nt) hist[b] = 0;
    for (int i = t; i < n; i += nt) agg_s[i] = 0.f;
    for (int c = t; c < 2 * d4; c += nt)
        wsm[c] = (c < d4) ? wrel4[c] : wroot4[c - d4];
    __syncthreads();

    // ---- Phase 1: dual dot products, 8 lanes per node, 4 nodes per warp ----
    {
        const float4* x4 = (const float4*)x;
        const float4* wa = wsm;
        const float4* wb = wsm + d4;
        const int w    = t >> 5;                  // warp 0..31
        const int lane = t & 31;
        const int sub  = lane >> 3;               // node-in-warp 0..3
        const int l8   = lane & 7;
        const int npp  = (nt >> 5) * 4;           // nodes per pass = 128
        for (int i0 = 0; i0 < n; i0 += npp) {
            int node = i0 + w * 4 + sub;
            const float4* xr = x4 + (size_t)(base + node) * d4;
            float sp = 0.f, sr = 0.f;
#pragma unroll 8
            for (int c = l8; c < d4; c += 8) {
                float4 xv = xr[c];
                float4 a  = wa[c];
                float4 b  = wb[c];
                sp += xv.x * a.x + xv.y * a.y + xv.z * a.z + xv.w * a.w;
                sr += xv.x * b.x + xv.y * b.y + xv.z * b.z + xv.w * b.w;
            }
#pragma unroll
            for (int o = 4; o; o >>= 1) {
                sp += __shfl_xor_sync(0xffffffffu, sp, o);
                sr += __shfl_xor_sync(0xffffffffu, sr, o);
            }
            if (l8 == 0) {
                p_s[node] = sp;
                r_s[node] = sr;
            }
        }
    }
    __syncthreads();

    // ---- Phase 2: edge scatter-add from registers (LDS + ATOMS only) ----
    {
#pragma unroll
        for (int q = 0; q < EPT; q++)
            if (ed[q] >= 0) atomicAdd(&agg_s[ed[q]], p_s[es[q]]);
        // remainder (if Eg > EPT*nt — not hit for this shape)
        for (int e = EPT * nt + t; e < Eg; e += nt) {
            const int eb = g * Eg;
            atomicAdd(&agg_s[ei[eb + e] - base], p_s[ei[eb + e - Eg + Eg] - base]);
        }
    }
    __syncthreads();

    // ---- Phase 3a: tanh score -> monotone bits (register) + histogram ----
    unsigned myu = 0;
    if (t < n) {
        float s = tanhf(agg_s[t] + br + r_s[t]);
        unsigned u = __float_as_uint(s);
        myu = (u & 0x80000000u) ? ~u : (u | 0x80000000u);
        atomicAdd(&hist[myu >> 24], 1u);
    }
    __syncthreads();

    // ---- Phase 3b: suffix counts via warp shuffle scan ----
    unsigned h_b = 0, s_in = 0;
    if (t < 256) {
        h_b  = hist[t];
        s_in = h_b;
        unsigned lane = t & 31;
#pragma unroll
        for (int off = 1; off < 32; off <<= 1) {
            unsigned v = __shfl_down_sync(0xffffffffu, s_in, off);
            if (lane + off < 32) s_in += v;
        }
        if (lane == 0) wtot[t >> 5] = s_in;
    }
    __syncthreads();
    if (t < 256) {
        unsigned w = t >> 5;
        unsigned ws = 0;
        for (unsigned j = w + 1; j < 8; j++) ws += wtot[j];
        unsigned incl = s_in + ws;            // elems in buckets >= t
        unsigned excl = incl - h_b;           // elems in buckets >  t
        if (excl < (unsigned)k && (unsigned)k <= incl) {
            ctrl[2] = t;                      // threshold bucket
            ctrl[3] = k - (int)excl;          // take this many from it
        }
    }
    __syncthreads();

    const int tb   = ctrl[2];
    const int krem = ctrl[3];

    // ---- Phase 3c: emit clear winners; threshold bucket -> fine list ----
    if (t < n) {
        int b = (int)(myu >> 24);
        if (b > tb) {
            int pos = atomicAdd(&ctrl[0], 1);
            unsigned fu = (myu & 0x80000000u) ? (myu & 0x7fffffffu) : ~myu;
            svals[pos] = __uint_as_float(fu);
            sidx[pos]  = t;
        } else if (b == tb) {
            int pos = atomicAdd(&ctrl[1], 1);
            list[pos] = make_uint2(myu, (unsigned)t);
        }
    }
    __syncthreads();

    // ---- Phase 3d: fine rank within threshold bucket (smaller idx wins) ----
    {
        const int m = ctrl[1];
        if (t < m) {
            uint2 me = list[t];
            int r = 0;
            for (int l = 0; l < m; l++) {
                uint2 o = list[l];
                r += (o.x > me.x) || (o.x == me.x && o.y < me.y);
            }
            if (r < krem) {
                int pos = atomicAdd(&ctrl[0], 1);
                unsigned fu = (me.x & 0x80000000u) ? (me.x & 0x7fffffffu) : ~me.x;
                svals[pos] = __uint_as_float(fu);
                sidx[pos]  = (int)me.y;
            }
        }
    }
    __syncthreads();

    // ---- Phase 4: weighted mean, float4 gather (rows hot in L1/L2) ----
    {
        const int col4 = t % d4;
        const int rep  = t / d4;
        const int per  = (k + nrep4 - 1) / nrep4;
        const int j0   = rep * per;
        const int j1   = min(j0 + per, k);
        const float4* x4 = (const float4*)x;
        float4 a0 = {0,0,0,0}, a1 = {0,0,0,0}, a2 = {0,0,0,0}, a3 = {0,0,0,0};
        int j = j0;
        for (; j + 4 <= j1; j += 4) {
            float v0 = svals[j], v1 = svals[j+1], v2 = svals[j+2], v3 = svals[j+3];
            int   r0 = sidx[j],  r1 = sidx[j+1],  r2 = sidx[j+2],  r3 = sidx[j+3];
            float4 q0 = x4[(size_t)(base + r0) * d4 + col4];
            float4 q1 = x4[(size_t)(base + r1) * d4 + col4];
            float4 q2 = x4[(size_t)(base + r2) * d4 + col4];
            float4 q3 = x4[(size_t)(base + r3) * d4 + col4];
            a0.x += v0*q0.x; a0.y += v0*q0.y; a0.z += v0*q0.z; a0.w += v0*q0.w;
            a1.x += v1*q1.x; a1.y += v1*q1.y; a1.z += v1*q1.z; a1.w += v1*q1.w;
            a2.x += v2*q2.x; a2.y += v2*q2.y; a2.z += v2*q2.z; a2.w += v2*q2.w;
            a3.x += v3*q3.x; a3.y += v3*q3.y; a3.z += v3*q3.z; a3.w += v3*q3.w;
        }
        for (; j < j1; j++) {
            float v = svals[j];
            float4 q = x4[(size_t)(base + sidx[j]) * d4 + col4];
            a0.x += v*q.x; a0.y += v*q.y; a0.z += v*q.z; a0.w += v*q.w;
        }
        float4 s;
        s.x = a0.x + a1.x + a2.x + a3.x;
        s.y = a0.y + a1.y + a2.y + a3.y;
        s.z = a0.z + a1.z + a2.z + a3.z;
        s.w = a0.w + a1.w + a2.w + a3.w;
        ((float4*)part)[rep * d4 + col4] = s;
    }
    __syncthreads();

    if (t < d) {
        float s = 0.f;
        for (int rr = 0; rr < nrep4; rr++) s += part[rr * d + t];
        pooled[t] = s / (float)k;
    }
    __syncthreads();

    // ---- Phase 5: vectorized projection ----
    {
        const int od4   = odim >> 2;
        const int o4    = t % od4;
        const int rep   = t / od4;
        const int nrepP = nt / od4;
        const int chunk = d / nrepP;
        const int d0 = rep * chunk, d1 = d0 + chunk;
        const float4* w4 = (const float4*)wproj;
        float4 acc = {0, 0, 0, 0};
#pragma unroll 4
        for (int dd = d0; dd < d1; dd++) {
            float pv = pooled[dd];
            float4 w = w4[(size_t)dd * od4 + o4];
            acc.x += pv * w.x; acc.y += pv * w.y;
            acc.z += pv * w.z; acc.w += pv * w.w;
        }
        ((float4*)part)[rep * od4 + o4] = acc;
    }
    __syncthreads();

    {
        const int od4   = odim >> 2;
        const int nrepP = nt / od4;
        if (t < od4) {
            float4 acc = ((float4*)part)[t];
            for (int rr = 1; rr < nrepP; rr++) {
                float4 q = ((float4*)part)[rr * od4 + t];
                acc.x += q.x; acc.y += q.y; acc.z += q.z; acc.w += q.w;
            }
            float4 b = ((const float4*)bproj)[t];
            float4 o;
            o.x = acc.x + b.x; o.y = acc.y + b.y;
            o.z = acc.z + b.z; o.w = acc.w + b.w;
            ((float4*)out)[(size_t)g * od4 + t] = o;
        }
    }
}

// ---------------------------------------------------------------------------
// Inputs: x, edge_index, batch, num_graphs, w_rel, b_rel, w_root, w_proj, b_proj.
// Output: [B, out_dim] float32.
// ---------------------------------------------------------------------------
extern "C" void kernel_launch(void* const* d_in, const int* in_sizes, int n_in,
                              void* d_out, int out_size) {
    const float* x     = (const float*)d_in[0];
    const int*   ei    = (const int*)d_in[1];
    const float* wrel  = (const float*)d_in[4];
    const float* brel  = (const float*)d_in[5];
    const float* wroot = (const float*)d_in[6];
    const float* wproj = (const float*)d_in[7];
    const float* bproj = (const float*)d_in[8];
    float* out = (float*)d_out;

    const int odim = in_sizes[8];
    const int d    = in_sizes[7] / odim;
    const int N    = in_sizes[0] / d;
    const int E    = in_sizes[1] / 2;
    const int B    = out_size / odim;
    const int n    = N / B;
    const int k    = (n + 1) / 2;     // ceil(0.5 * n), RATIO = 0.5
    const int Eg   = E / B;
    const int d4   = d / 4;
    const int nrep4 = 1024 / d4;      // 16 for d=256

    const int pd = d > odim ? d : odim;
    size_t smem = (size_t)(2 * d4) * 16          // weights
                + (size_t)n * 12                 // p, r, agg
                + (size_t)k * 8                  // svals + sidx
                + 264 * 4                        // hist + wtot
                + (size_t)n * 8                  // fine list
                + (size_t)nrep4 * pd * 4         // part
                + (size_t)d * 4                  // pooled
                + 32;                            // ctrl + pad
    k_fused<<<B, 1024, smem>>>(x, ei, (const float4*)wrel, brel,
                               (const float4*)wroot, wproj, bproj, out,
                               n, k, d, odim, E, Eg, nrep4);
}